// round 7
// baseline (speedup 1.0000x reference)
#include <cuda_runtime.h>
#include <cuda_bf16.h>
#include <cstdint>

// ---------------------------------------------------------------------------
// B=131072, chain 512 ->(W1)512 ->(W2)128 ->(W3)32 ->(W4)8 ->(Wh)1
// GEMM1: A = fp32 x via LDG->reg-split->STS bf16 (no split_x kernel),
//        B = W1 bf16 hi/lo 3-stage cp.async ring, HMMA bf16x3,
//        epilogue bias + h1raw + per-colblock LN partials.
// GEMM2: A = h1raw via LDG->LN1+CELU+split in regs->STS, HMMA bf16x3,
//        epilogue LN2+CELU -> h2. Both 2 CTAs/SM.
// ---------------------------------------------------------------------------

#define BATCH 131072

__device__ __align__(256) float         g_h1raw[BATCH * 512];
__device__ __align__(256) float         g_h2   [BATCH * 128];
__device__ __align__(256) float2        g_part [4 * BATCH];
__device__ __align__(256) __nv_bfloat16 g_w1hi [512 * 512];
__device__ __align__(256) __nv_bfloat16 g_w1lo [512 * 512];
__device__ __align__(256) __nv_bfloat16 g_w2hi [128 * 512];
__device__ __align__(256) __nv_bfloat16 g_w2lo [128 * 512];

// ------------------------------ helpers ------------------------------------
__device__ __forceinline__ uint32_t smem_u32(const void* p) {
    uint32_t a;
    asm("{ .reg .u64 t; cvta.to.shared.u64 t, %1; cvt.u32.u64 %0, t; }"
        : "=r"(a) : "l"(p));
    return a;
}
__device__ __forceinline__ void cp_async16(uint32_t dst, const void* src) {
    asm volatile("cp.async.cg.shared.global [%0], [%1], 16;"
                 :: "r"(dst), "l"(src) : "memory");
}
#define CP_COMMIT() asm volatile("cp.async.commit_group;" ::: "memory")
#define CP_WAIT(n)  asm volatile("cp.async.wait_group %0;" :: "n"(n) : "memory")

__device__ __forceinline__ void ldmx4(uint32_t& r0, uint32_t& r1,
                                      uint32_t& r2, uint32_t& r3, uint32_t a) {
    asm volatile("ldmatrix.sync.aligned.m8n8.x4.shared.b16 {%0,%1,%2,%3}, [%4];"
                 : "=r"(r0), "=r"(r1), "=r"(r2), "=r"(r3) : "r"(a));
}
__device__ __forceinline__ void mma16816(float& c0, float& c1, float& c2, float& c3,
                                         uint32_t a0, uint32_t a1, uint32_t a2, uint32_t a3,
                                         uint32_t b0, uint32_t b1) {
    asm volatile("mma.sync.aligned.m16n8k16.row.col.f32.bf16.bf16.f32 "
                 "{%0,%1,%2,%3}, {%4,%5,%6,%7}, {%8,%9}, {%0,%1,%2,%3};"
                 : "+f"(c0), "+f"(c1), "+f"(c2), "+f"(c3)
                 : "r"(a0), "r"(a1), "r"(a2), "r"(a3), "r"(b0), "r"(b1));
}
__device__ __forceinline__ float warp_sum(float v) {
#pragma unroll
    for (int o = 16; o; o >>= 1) v += __shfl_xor_sync(0xffffffffu, v, o);
    return v;
}
__device__ __forceinline__ uint32_t swz(uint32_t row, uint32_t q) {
    return row * 64 + (q ^ ((row & 6u) >> 1)) * 16;
}
__device__ __forceinline__ float celu1(float y) {
    return (y > 0.f) ? y : expm1f(y);
}
__device__ __forceinline__ uint32_t pack_bf16(float a0, float a1) {
    __nv_bfloat162 t; t.x = __float2bfloat16(a0); t.y = __float2bfloat16(a1);
    return *reinterpret_cast<uint32_t*>(&t);
}
// split two fp32 into packed hi / packed lo bf16x2
__device__ __forceinline__ void split2(float a0, float a1, uint32_t& hp, uint32_t& lp) {
    __nv_bfloat16 h0 = __float2bfloat16(a0), h1 = __float2bfloat16(a1);
    hp = (uint32_t)__bfloat16_as_ushort(h1) << 16 | (uint32_t)__bfloat16_as_ushort(h0);
    lp = pack_bf16(a0 - __bfloat162float(h0), a1 - __bfloat162float(h1));
}

// smem layout constants (shared by both GEMMs)
//  [0, 49152)  B ring: 3 stages x (Bhi 8192 + Blo 8192)
//  [49152, 81920) A tiles: 2 bufs x (Ahi 8192 + Alo 8192)
#define B_STG   16384
#define OFF_BLO 8192
#define OFF_A   49152
#define A_STG   16384
#define OFF_ALO 8192
#define SMEM_DYN 81920

// ---------------------------------------------------------------------------
// Split fp32 -> bf16 hi + lo (weights only now).
// ---------------------------------------------------------------------------
__global__ void __launch_bounds__(256)
split_kernel(const float* __restrict__ src, __nv_bfloat16* __restrict__ hi,
             __nv_bfloat16* __restrict__ lo, int n4)
{
    int i = blockIdx.x * blockDim.x + threadIdx.x;
    if (i >= n4) return;
    float4 v = reinterpret_cast<const float4*>(src)[i];
    uint32_t h0, l0, h1, l1;
    split2(v.x, v.y, h0, l0);
    split2(v.z, v.w, h1, l1);
    reinterpret_cast<uint32_t*>(hi)[2 * i]     = h0;
    reinterpret_cast<uint32_t*>(hi)[2 * i + 1] = h1;
    reinterpret_cast<uint32_t*>(lo)[2 * i]     = l0;
    reinterpret_cast<uint32_t*>(lo)[2 * i + 1] = l1;
}

// ---------------------------------------------------------------------------
// Shared MMA inner step (A tiles at sa, B tiles at sbB) -> acc
// ---------------------------------------------------------------------------
__device__ __forceinline__ void mma_stage(uint32_t sa, uint32_t sbB,
                                          int lane, int warpM, int warpN,
                                          float acc[4][4][4])
{
#pragma unroll
    for (int ks = 0; ks < 2; ks++) {
        uint32_t ah[4][4], al[4][4];
        const uint32_t arow = warpM * 64 + (lane & 15);
        const uint32_t aq   = ks * 2 + (lane >> 4);
#pragma unroll
        for (int mt = 0; mt < 4; mt++) {
            const uint32_t adr = sa + swz(arow + mt * 16, aq);
            ldmx4(ah[mt][0], ah[mt][1], ah[mt][2], ah[mt][3], adr);
            ldmx4(al[mt][0], al[mt][1], al[mt][2], al[mt][3], adr + OFF_ALO);
        }
        const uint32_t brow0 = warpN * 32 + (lane & 7) + ((lane >> 4) & 1) * 8;
        const uint32_t bq    = ks * 2 + ((lane >> 3) & 1);
#pragma unroll
        for (int pr = 0; pr < 2; pr++) {
            uint32_t bh0, bh1, bh2, bh3, bl0, bl1, bl2, bl3;
            const uint32_t adr = sbB + swz(brow0 + pr * 16, bq);
            ldmx4(bh0, bh1, bh2, bh3, adr);
            ldmx4(bl0, bl1, bl2, bl3, adr + OFF_BLO);
#pragma unroll
            for (int mt = 0; mt < 4; mt++) {
                float* c0 = acc[mt][2 * pr];
                mma16816(c0[0], c0[1], c0[2], c0[3],
                         ah[mt][0], ah[mt][1], ah[mt][2], ah[mt][3], bh0, bh1);
                mma16816(c0[0], c0[1], c0[2], c0[3],
                         ah[mt][0], ah[mt][1], ah[mt][2], ah[mt][3], bl0, bl1);
                mma16816(c0[0], c0[1], c0[2], c0[3],
                         al[mt][0], al[mt][1], al[mt][2], al[mt][3], bh0, bh1);
                float* c1 = acc[mt][2 * pr + 1];
                mma16816(c1[0], c1[1], c1[2], c1[3],
                         ah[mt][0], ah[mt][1], ah[mt][2], ah[mt][3], bh2, bh3);
                mma16816(c1[0], c1[1], c1[2], c1[3],
                         ah[mt][0], ah[mt][1], ah[mt][2], ah[mt][3], bl2, bl3);
                mma16816(c1[0], c1[1], c1[2], c1[3],
                         al[mt][0], al[mt][1], al[mt][2], al[mt][3], bh2, bh3);
            }
        }
    }
}

// ---------------------------------------------------------------------------
// GEMM1: h1raw[M,512] = x @ W1^T + b1 (fp32), A from fp32 x (reg split),
// per-colblock LN partials to gpart.
// ---------------------------------------------------------------------------
__global__ void __launch_bounds__(256, 2)
gemm1_fused_kernel(const float* __restrict__ X,
                   const __nv_bfloat16* __restrict__ Bhi, const __nv_bfloat16* __restrict__ Blo,
                   const float* __restrict__ bias, float* __restrict__ C,
                   float2* __restrict__ gpart, int Mtot)
{
    constexpr int K = 512;
    constexpr int NSTAGES = K / 32;
    extern __shared__ char smem[];
    __shared__ float2 sred[4][128];
    const uint32_t sb = smem_u32(smem);

    const int tid   = threadIdx.x;
    const int lane  = tid & 31;
    const int wid   = tid >> 5;
    const int warpM = wid >> 2;
    const int warpN = wid & 3;
    const size_t rowBase = (size_t)blockIdx.y * 128;
    const int    colBase = blockIdx.x * 128;

    const int c0r = tid >> 2,  cq = tid & 3;
    const int c1r = 64 + (tid >> 2);
    const uint32_t d0 = swz(c0r, cq);
    const uint32_t d1 = swz(c1r, cq);

    // A convert slot: row (tid>>1), 16 cols at (tid&1)*16
    const int crow  = tid >> 1;
    const int chalf = tid & 1;
    const float* xrow = X + (rowBase + crow) * K + chalf * 16;

    float acc[4][4][4];
#pragma unroll
    for (int i = 0; i < 4; i++)
#pragma unroll
        for (int j = 0; j < 4; j++)
#pragma unroll
            for (int q = 0; q < 4; q++) acc[i][j][q] = 0.f;

    float4 fA[4];
    auto prefetchA = [&](int t) {
        const float* p = xrow + t * 32;
#pragma unroll
        for (int j = 0; j < 4; j++)
            fA[j] = *reinterpret_cast<const float4*>(p + j * 4);
    };
    auto load_B = [&](int t) {
        const int k0 = t * 32;
        const uint32_t s = sb + (t % 3) * B_STG;
        const size_t g0 = (size_t)(colBase + c0r) * K + k0 + cq * 8;
        const size_t g1 = (size_t)(colBase + c1r) * K + k0 + cq * 8;
        cp_async16(s + d0,           Bhi + g0);
        cp_async16(s + d1,           Bhi + g1);
        cp_async16(s + OFF_BLO + d0, Blo + g0);
        cp_async16(s + OFF_BLO + d1, Blo + g1);
        CP_COMMIT();
    };

    prefetchA(0);
    load_B(0);
    load_B(1);

#pragma unroll 1
    for (int t = 0; t < NSTAGES; t++) {
        // convert A(t): pure bf16 split, regs -> smem tiles
        {
            const uint32_t sa = sb + OFF_A + (t & 1) * A_STG;
            uint32_t hw[8], lw[8];
#pragma unroll
            for (int j = 0; j < 4; j++) {
                split2(fA[j].x, fA[j].y, hw[2 * j],     lw[2 * j]);
                split2(fA[j].z, fA[j].w, hw[2 * j + 1], lw[2 * j + 1]);
            }
            const uint32_t q2 = chalf * 2;
            *reinterpret_cast<uint4*>(smem + (sa - sb) + swz(crow, q2)) =
                make_uint4(hw[0], hw[1], hw[2], hw[3]);
            *reinterpret_cast<uint4*>(smem + (sa - sb) + swz(crow, q2 + 1)) =
                make_uint4(hw[4], hw[5], hw[6], hw[7]);
            *reinterpret_cast<uint4*>(smem + (sa - sb) + OFF_ALO + swz(crow, q2)) =
                make_uint4(lw[0], lw[1], lw[2], lw[3]);
            *reinterpret_cast<uint4*>(smem + (sa - sb) + OFF_ALO + swz(crow, q2 + 1)) =
                make_uint4(lw[4], lw[5], lw[6], lw[7]);
        }
        if (t + 1 < NSTAGES) prefetchA(t + 1);
        if (t + 1 < NSTAGES) { CP_WAIT(1); } else { CP_WAIT(0); }
        __syncthreads();
        if (t + 2 < NSTAGES) load_B(t + 2);

        mma_stage(sb + OFF_A + (t & 1) * A_STG, sb + (t % 3) * B_STG,
                  lane, warpM, warpN, acc);
        __syncthreads();   // A buffer t&1 reused at t+2; B ring guarded by waits
    }

    // ---- epilogue: + bias, fp32 out, per-row partials ----
#pragma unroll
    for (int mt = 0; mt < 4; mt++) {
        const int rloc = warpM * 64 + mt * 16 + (lane >> 2);
        const size_t r0 = rowBase + rloc;
        float s0 = 0.f, q0 = 0.f, s1 = 0.f, q1 = 0.f;
#pragma unroll
        for (int nt = 0; nt < 4; nt++) {
            const int col = colBase + warpN * 32 + nt * 8 + (lane & 3) * 2;
            const float b0 = bias[col], b1 = bias[col + 1];
            float* c = acc[mt][nt];
            const float v00 = c[0] + b0, v01 = c[1] + b1;
            const float v10 = c[2] + b0, v11 = c[3] + b1;
            *reinterpret_cast<float2*>(C + r0 * 512 + col)       = make_float2(v00, v01);
            *reinterpret_cast<float2*>(C + (r0 + 8) * 512 + col) = make_float2(v10, v11);
            s0 += v00 + v01; q0 += v00 * v00 + v01 * v01;
            s1 += v10 + v11; q1 += v10 * v10 + v11 * v11;
        }
#pragma unroll
        for (int o = 1; o <= 2; o <<= 1) {
            s0 += __shfl_xor_sync(0xffffffffu, s0, o);
            q0 += __shfl_xor_sync(0xffffffffu, q0, o);
            s1 += __shfl_xor_sync(0xffffffffu, s1, o);
            q1 += __shfl_xor_sync(0xffffffffu, q1, o);
        }
        if ((lane & 3) == 0) {
            sred[warpN][rloc]     = make_float2(s0, q0);
            sred[warpN][rloc + 8] = make_float2(s1, q1);
        }
    }
    __syncthreads();
    if (tid < 128) {
        float s = 0.f, q = 0.f;
#pragma unroll
        for (int w = 0; w < 4; w++) { s += sred[w][tid].x; q += sred[w][tid].y; }
        gpart[(size_t)blockIdx.x * Mtot + rowBase + tid] = make_float2(s, q);
    }
}

// ---------------------------------------------------------------------------
// GEMM2 fused: a1 = celu(LN1(h1raw)) in regs -> HMMA bf16x3 -> LN2+CELU -> h2
// ---------------------------------------------------------------------------
__global__ void __launch_bounds__(256, 2)
gemm2_fused_kernel(const float* __restrict__ h1raw, const float2* __restrict__ gpart,
                   const float* __restrict__ g1, const float* __restrict__ be1,
                   const __nv_bfloat16* __restrict__ Bhi, const __nv_bfloat16* __restrict__ Blo,
                   const float* __restrict__ b2, const float* __restrict__ g2,
                   const float* __restrict__ be2,
                   float* __restrict__ h2, int Mtot)
{
    constexpr int K = 512;
    constexpr int NSTAGES = K / 32;
    extern __shared__ char smem[];
    __shared__ float  smu[128], srstd[128];
    __shared__ float  sg1[512], sbe1[512];
    __shared__ float  sg2[128], sbe2[128], sb2[128];
    __shared__ float2 sred[4][128];
    const uint32_t sb = smem_u32(smem);

    const int tid   = threadIdx.x;
    const int lane  = tid & 31;
    const int wid   = tid >> 5;
    const int warpM = wid >> 2;
    const int warpN = wid & 3;
    const size_t rowBase = (size_t)blockIdx.x * 128;

    if (tid < 128) {
        float s = 0.f, q = 0.f;
#pragma unroll
        for (int b = 0; b < 4; b++) {
            float2 p = gpart[(size_t)b * Mtot + rowBase + tid];
            s += p.x; q += p.y;
        }
        const float mu = s * (1.f / 512.f);
        smu[tid]   = mu;
        srstd[tid] = rsqrtf(q * (1.f / 512.f) - mu * mu + 1e-5f);
        sg2[tid] = g2[tid]; sbe2[tid] = be2[tid]; sb2[tid] = b2[tid];
    }
#pragma unroll
    for (int i = tid; i < 512; i += 256) { sg1[i] = g1[i]; sbe1[i] = be1[i]; }
    __syncthreads();

    const int c0r = tid >> 2,  cq = tid & 3;
    const int c1r = 64 + (tid >> 2);
    const uint32_t d0 = swz(c0r, cq);
    const uint32_t d1 = swz(c1r, cq);

    const int crow  = tid >> 1;
    const int chalf = tid & 1;
    const float* arow = h1raw + (rowBase + crow) * K + chalf * 16;
    const float cmu = smu[crow], crs = srstd[crow];

    float acc[4][4][4];
#pragma unroll
    for (int i = 0; i < 4; i++)
#pragma unroll
        for (int j = 0; j < 4; j++)
#pragma unroll
            for (int q = 0; q < 4; q++) acc[i][j][q] = 0.f;

    float4 fA[4];
    auto prefetchA = [&](int t) {
        const float* p = arow + t * 32;
#pragma unroll
        for (int j = 0; j < 4; j++)
            fA[j] = *reinterpret_cast<const float4*>(p + j * 4);
    };
    auto load_B = [&](int t) {
        const int k0 = t * 32;
        const uint32_t s = sb + (t % 3) * B_STG;
        const size_t g0 = (size_t)c0r * K + k0 + cq * 8;
        const size_t g1 = (size_t)c1r * K + k0 + cq * 8;
        cp_async16(s + d0,           Bhi + g0);
        cp_async16(s + d1,           Bhi + g1);
        cp_async16(s + OFF_BLO + d0, Blo + g0);
        cp_async16(s + OFF_BLO + d1, Blo + g1);
        CP_COMMIT();
    };

    prefetchA(0);
    load_B(0);
    load_B(1);

#pragma unroll 1
    for (int t = 0; t < NSTAGES; t++) {
        // convert A(t): LN1 + CELU + split, regs -> smem tiles
        {
            const int k0 = t * 32 + chalf * 16;
            const uint32_t abase = OFF_A + (t & 1) * A_STG;
            uint32_t hw[8], lw[8];
#pragma unroll
            for (int j = 0; j < 4; j++) {
                const float vv[4] = { fA[j].x, fA[j].y, fA[j].z, fA[j].w };
#pragma unroll
                for (int e = 0; e < 2; e++) {
                    const int col = k0 + j * 4 + e * 2;
                    float a0 = celu1((vv[2*e]   - cmu) * crs * sg1[col]     + sbe1[col]);
                    float a1 = celu1((vv[2*e+1] - cmu) * crs * sg1[col + 1] + sbe1[col + 1]);
                    split2(a0, a1, hw[2 * j + e], lw[2 * j + e]);
                }
            }
            const uint32_t q2 = chalf * 2;
            *reinterpret_cast<uint4*>(smem + abase + swz(crow, q2)) =
                make_uint4(hw[0], hw[1], hw[2], hw[3]);
            *reinterpret_cast<uint4*>(smem + abase + swz(crow, q2 + 1)) =
                make_uint4(hw[4], hw[5], hw[6], hw[7]);
            *reinterpret_cast<uint4*>(smem + abase + OFF_ALO + swz(crow, q2)) =
                make_uint4(lw[0], lw[1], lw[2], lw[3]);
            *reinterpret_cast<uint4*>(smem + abase + OFF_ALO + swz(crow, q2 + 1)) =
                make_uint4(lw[4], lw[5], lw[6], lw[7]);
        }
        if (t + 1 < NSTAGES) prefetchA(t + 1);
        if (t + 1 < NSTAGES) { CP_WAIT(1); } else { CP_WAIT(0); }
        __syncthreads();
        if (t + 2 < NSTAGES) load_B(t + 2);

        mma_stage(sb + OFF_A + (t & 1) * A_STG, sb + (t % 3) * B_STG,
                  lane, warpM, warpN, acc);
        __syncthreads();
    }

    // ---- epilogue: bias2, LN2 over full rows, CELU -> h2 ----
#pragma unroll
    for (int mt = 0; mt < 4; mt++) {
        const int rloc = warpM * 64 + mt * 16 + (lane >> 2);
        float s0 = 0.f, q0 = 0.f, s1 = 0.f, q1 = 0.f;
#pragma unroll
        for (int nt = 0; nt < 4; nt++) {
            const int col = warpN * 32 + nt * 8 + (lane & 3) * 2;
            const float b0 = sb2[col], b1 = sb2[col + 1];
            float* c = acc[mt][nt];
            const float v00 = c[0] + b0, v01 = c[1] + b1;
            const float v10 = c[2] + b0, v11 = c[3] + b1;
            s0 += v00 + v01; q0 += v00 * v00 + v01 * v01;
            s1 += v10 + v11; q1 += v10 * v10 + v11 * v11;
        }
#pragma unroll
        for (int o = 1; o <= 2; o <<= 1) {
            s0 += __shfl_xor_sync(0xffffffffu, s0, o);
            q0 += __shfl_xor_sync(0xffffffffu, q0, o);
            s1 += __shfl_xor_sync(0xffffffffu, s1, o);
            q1 += __shfl_xor_sync(0xffffffffu, q1, o);
        }
        if ((lane & 3) == 0) {
            sred[warpN][rloc]     = make_float2(s0, q0);
            sred[warpN][rloc + 8] = make_float2(s1, q1);
        }
    }
    __syncthreads();
    if (tid < 128) {
        float s = 0.f, q = 0.f;
#pragma unroll
        for (int w = 0; w < 4; w++) { s += sred[w][tid].x; q += sred[w][tid].y; }
        const float mu = s * (1.f / 128.f);
        smu[tid]   = mu;
        srstd[tid] = rsqrtf(q * (1.f / 128.f) - mu * mu + 1e-5f);
    }
    __syncthreads();
#pragma unroll
    for (int mt = 0; mt < 4; mt++) {
        const int rloc = warpM * 64 + mt * 16 + (lane >> 2);
        const float mu0 = smu[rloc],     rs0 = srstd[rloc];
        const float mu1 = smu[rloc + 8], rs1 = srstd[rloc + 8];
        const size_t r0 = rowBase + rloc;
#pragma unroll
        for (int nt = 0; nt < 4; nt++) {
            const int col = warpN * 32 + nt * 8 + (lane & 3) * 2;
            const float b0 = sb2[col], b1 = sb2[col + 1];
            float* c = acc[mt][nt];
            float y00 = (c[0] + b0 - mu0) * rs0 * sg2[col]     + sbe2[col];
            float y01 = (c[1] + b1 - mu0) * rs0 * sg2[col + 1] + sbe2[col + 1];
            float y10 = (c[2] + b0 - mu1) * rs1 * sg2[col]     + sbe2[col];
            float y11 = (c[3] + b1 - mu1) * rs1 * sg2[col + 1] + sbe2[col + 1];
            *reinterpret_cast<float2*>(h2 + r0 * 128 + col) =
                make_float2(celu1(y00), celu1(y01));
            *reinterpret_cast<float2*>(h2 + (r0 + 8) * 128 + col) =
                make_float2(celu1(y10), celu1(y11));
        }
    }
}

// ---------------------------------------------------------------------------
// Tail: layer3 (128->32)+LN+CELU, layer4 (32->8)+LN+CELU, spectral-norm head.
// ---------------------------------------------------------------------------
__global__ void __launch_bounds__(256)
tail_kernel(const float* __restrict__ h2,
            const float* __restrict__ W3, const float* __restrict__ b3,
            const float* __restrict__ g3, const float* __restrict__ be3,
            const float* __restrict__ W4, const float* __restrict__ b4,
            const float* __restrict__ g4, const float* __restrict__ be4,
            const float* __restrict__ Wh, const float* __restrict__ bh,
            const float* __restrict__ u, float* __restrict__ out)
{
    __shared__ float sW3[32 * 128];
    __shared__ float sW4[8 * 32];
    const int tid = threadIdx.x;
    for (int i = tid; i < 32 * 128; i += 256) sW3[i] = W3[i];
    if (tid < 8 * 32) sW4[tid] = W4[tid];
    __syncthreads();

    const int lane = tid & 31;
    const size_t row = (size_t)blockIdx.x * 8 + (tid >> 5);
    const float* rp = h2 + row * 128;
    const float r0 = rp[lane], r1 = rp[lane + 32], r2 = rp[lane + 64], r3 = rp[lane + 96];

    float h3 = 0.f;
#pragma unroll
    for (int j = 0; j < 32; j++) {
        const float* w = sW3 + j * 128;
        float p = r0 * w[lane] + r1 * w[lane + 32] + r2 * w[lane + 64] + r3 * w[lane + 96];
        p = warp_sum(p);
        if (lane == j) h3 = p + b3[j];
    }
    float mu  = warp_sum(h3) * (1.f / 32.f);
    float d   = h3 - mu;
    float var = warp_sum(d * d) * (1.f / 32.f);
    float y3  = d * rsqrtf(var + 1e-5f) * g3[lane] + be3[lane];
    const float c3 = (y3 > 0.f) ? y3 : expm1f(y3);

    float h4 = 0.f;
#pragma unroll
    for (int j = 0; j < 8; j++) {
        float p = warp_sum(c3 * sW4[j * 32 + lane]);
        if (lane == j) h4 = p + b4[j];
    }
    const bool act = (lane < 8);
    float hv = act ? h4 : 0.f;
    mu  = warp_sum(hv) * 0.125f;
    d   = act ? (h4 - mu) : 0.f;
    var = warp_sum(d * d) * 0.125f;
    float c4 = 0.f;
    if (act) {
        float y4 = d * rsqrtf(var + 1e-5f) * g4[lane] + be4[lane];
        c4 = (y4 > 0.f) ? y4 : expm1f(y4);
    }

    const float wh  = act ? Wh[lane] : 0.f;
    const float nrm = sqrtf(warp_sum(wh * wh));
    const float u0  = u[0];
    const float vden = fabsf(u0) * nrm + 1e-12f;
    const float t    = u0 * nrm * nrm / vden;
    const float u2n  = t / (fabsf(t) + 1e-12f);
    const float sigma = u2n * t;

    float p = warp_sum(c4 * wh / sigma);
    if (lane == 0) out[row] = p + bh[0];
}

// ---------------------------------------------------------------------------
extern "C" void kernel_launch(void* const* d_in, const int* in_sizes, int n_in,
                              void* d_out, int out_size)
{
    const float* x   = (const float*)d_in[0];
    const float* W1  = (const float*)d_in[1];
    const float* b1  = (const float*)d_in[2];
    const float* g1  = (const float*)d_in[3];
    const float* be1 = (const float*)d_in[4];
    const float* W2  = (const float*)d_in[5];
    const float* b2  = (const float*)d_in[6];
    const float* g2  = (const float*)d_in[7];
    const float* be2 = (const float*)d_in[8];
    const float* W3  = (const float*)d_in[9];
    const float* b3  = (const float*)d_in[10];
    const float* g3  = (const float*)d_in[11];
    const float* be3 = (const float*)d_in[12];
    const float* W4  = (const float*)d_in[13];
    const float* b4  = (const float*)d_in[14];
    const float* g4  = (const float*)d_in[15];
    const float* be4 = (const float*)d_in[16];
    const float* Wh  = (const float*)d_in[17];
    const float* bh  = (const float*)d_in[18];
    const float* u   = (const float*)d_in[19];
    float* out = (float*)d_out;

    const int M = in_sizes[0] / 512;   // 131072

    __nv_bfloat16 *w1hi, *w1lo, *w2hi, *w2lo;
    float *h1raw, *h2;
    float2* part;
    cudaGetSymbolAddress((void**)&h1raw, g_h1raw);
    cudaGetSymbolAddress((void**)&h2,    g_h2);
    cudaGetSymbolAddress((void**)&part,  g_part);
    cudaGetSymbolAddress((void**)&w1hi,  g_w1hi);
    cudaGetSymbolAddress((void**)&w1lo,  g_w1lo);
    cudaGetSymbolAddress((void**)&w2hi,  g_w2hi);
    cudaGetSymbolAddress((void**)&w2lo,  g_w2lo);

    cudaFuncSetAttribute(gemm1_fused_kernel,
                         cudaFuncAttributeMaxDynamicSharedMemorySize, SMEM_DYN);
    cudaFuncSetAttribute(gemm2_fused_kernel,
                         cudaFuncAttributeMaxDynamicSharedMemorySize, SMEM_DYN);

    // Split weights to bf16 hi/lo (small)
    split_kernel<<<(512 * 512 / 4 + 255) / 256, 256>>>(W1, w1hi, w1lo, 512 * 512 / 4);
    split_kernel<<<(128 * 512 / 4 + 255) / 256, 256>>>(W2, w2hi, w2lo, 128 * 512 / 4);

    // Layer 1: fused split(x)+GEMM -> h1raw fp32 + LN partials
    gemm1_fused_kernel<<<dim3(4, M / 128), 256, SMEM_DYN>>>(
        x, w1hi, w1lo, b1, h1raw, part, M);

    // Layer 2: fused LN1+CELU+split -> GEMM -> LN2+CELU -> h2
    gemm2_fused_kernel<<<M / 128, 256, SMEM_DYN>>>(
        h1raw, part, g1, be1, w2hi, w2lo, b2, g2, be2, h2, M);

    // Layers 3+4 + spectral-norm head
    tail_kernel<<<M / 8, 256>>>(h2, W3, b3, g3, be3, W4, b4, g4, be4, Wh, bh, u, out);
}

// round 8
// speedup vs baseline: 1.0515x; 1.0515x over previous
#include <cuda_runtime.h>
#include <cuda_bf16.h>
#include <cstdint>

// ---------------------------------------------------------------------------
// B=131072, chain 512 ->(W1)512 ->(W2)128 ->(W3)32 ->(W4)8 ->(Wh)1
// GEMM1: A = fp32 x, coalesced LDG -> reg split -> STS bf16 (3-buf A ring),
//        B = W1 bf16 hi/lo 3-stage cp.async ring, HMMA bf16x3, 1 barrier/stage.
// GEMM2: A = h1raw, LN1+CELU+split in regs, same structure; LN2+CELU epilogue.
// ---------------------------------------------------------------------------

#define BATCH 131072

__device__ __align__(256) float         g_h1raw[BATCH * 512];
__device__ __align__(256) float         g_h2   [BATCH * 128];
__device__ __align__(256) float2        g_part [4 * BATCH];
__device__ __align__(256) __nv_bfloat16 g_w1hi [512 * 512];
__device__ __align__(256) __nv_bfloat16 g_w1lo [512 * 512];
__device__ __align__(256) __nv_bfloat16 g_w2hi [128 * 512];
__device__ __align__(256) __nv_bfloat16 g_w2lo [128 * 512];

// ------------------------------ helpers ------------------------------------
__device__ __forceinline__ uint32_t smem_u32(const void* p) {
    uint32_t a;
    asm("{ .reg .u64 t; cvta.to.shared.u64 t, %1; cvt.u32.u64 %0, t; }"
        : "=r"(a) : "l"(p));
    return a;
}
__device__ __forceinline__ void cp_async16(uint32_t dst, const void* src) {
    asm volatile("cp.async.cg.shared.global [%0], [%1], 16;"
                 :: "r"(dst), "l"(src) : "memory");
}
#define CP_COMMIT() asm volatile("cp.async.commit_group;" ::: "memory")
#define CP_WAIT(n)  asm volatile("cp.async.wait_group %0;" :: "n"(n) : "memory")

__device__ __forceinline__ void ldmx4(uint32_t& r0, uint32_t& r1,
                                      uint32_t& r2, uint32_t& r3, uint32_t a) {
    asm volatile("ldmatrix.sync.aligned.m8n8.x4.shared.b16 {%0,%1,%2,%3}, [%4];"
                 : "=r"(r0), "=r"(r1), "=r"(r2), "=r"(r3) : "r"(a));
}
__device__ __forceinline__ void mma16816(float& c0, float& c1, float& c2, float& c3,
                                         uint32_t a0, uint32_t a1, uint32_t a2, uint32_t a3,
                                         uint32_t b0, uint32_t b1) {
    asm volatile("mma.sync.aligned.m16n8k16.row.col.f32.bf16.bf16.f32 "
                 "{%0,%1,%2,%3}, {%4,%5,%6,%7}, {%8,%9}, {%0,%1,%2,%3};"
                 : "+f"(c0), "+f"(c1), "+f"(c2), "+f"(c3)
                 : "r"(a0), "r"(a1), "r"(a2), "r"(a3), "r"(b0), "r"(b1));
}
__device__ __forceinline__ float warp_sum(float v) {
#pragma unroll
    for (int o = 16; o; o >>= 1) v += __shfl_xor_sync(0xffffffffu, v, o);
    return v;
}
__device__ __forceinline__ uint32_t swz(uint32_t row, uint32_t q) {
    return row * 64 + (q ^ ((row & 6u) >> 1)) * 16;
}
__device__ __forceinline__ float celu1(float y) {
    return (y > 0.f) ? y : expm1f(y);
}
__device__ __forceinline__ uint32_t pack_bf16(float a0, float a1) {
    __nv_bfloat162 t; t.x = __float2bfloat16(a0); t.y = __float2bfloat16(a1);
    return *reinterpret_cast<uint32_t*>(&t);
}
__device__ __forceinline__ void split2(float a0, float a1, uint32_t& hp, uint32_t& lp) {
    __nv_bfloat16 h0 = __float2bfloat16(a0), h1 = __float2bfloat16(a1);
    hp = (uint32_t)__bfloat16_as_ushort(h1) << 16 | (uint32_t)__bfloat16_as_ushort(h0);
    lp = pack_bf16(a0 - __bfloat162float(h0), a1 - __bfloat162float(h1));
}

// smem layout: B ring 3 x 16K at 0, A ring 3 x 16K at 49152.
#define B_STG   16384
#define OFF_BLO 8192
#define OFF_A   49152
#define A_STG   16384
#define OFF_ALO 8192
#define SMEM_DYN 98304

// ---------------------------------------------------------------------------
__global__ void __launch_bounds__(256)
split_kernel(const float* __restrict__ src, __nv_bfloat16* __restrict__ hi,
             __nv_bfloat16* __restrict__ lo, int n4)
{
    int i = blockIdx.x * blockDim.x + threadIdx.x;
    if (i >= n4) return;
    float4 v = reinterpret_cast<const float4*>(src)[i];
    uint32_t h0, l0, h1, l1;
    split2(v.x, v.y, h0, l0);
    split2(v.z, v.w, h1, l1);
    reinterpret_cast<uint32_t*>(hi)[2 * i]     = h0;
    reinterpret_cast<uint32_t*>(hi)[2 * i + 1] = h1;
    reinterpret_cast<uint32_t*>(lo)[2 * i]     = l0;
    reinterpret_cast<uint32_t*>(lo)[2 * i + 1] = l1;
}

// ---------------------------------------------------------------------------
__device__ __forceinline__ void mma_stage(uint32_t sa, uint32_t sbB,
                                          int lane, int warpM, int warpN,
                                          float acc[4][4][4])
{
#pragma unroll
    for (int ks = 0; ks < 2; ks++) {
        uint32_t ah[4][4], al[4][4];
        const uint32_t arow = warpM * 64 + (lane & 15);
        const uint32_t aq   = ks * 2 + (lane >> 4);
#pragma unroll
        for (int mt = 0; mt < 4; mt++) {
            const uint32_t adr = sa + swz(arow + mt * 16, aq);
            ldmx4(ah[mt][0], ah[mt][1], ah[mt][2], ah[mt][3], adr);
            ldmx4(al[mt][0], al[mt][1], al[mt][2], al[mt][3], adr + OFF_ALO);
        }
        const uint32_t brow0 = warpN * 32 + (lane & 7) + ((lane >> 4) & 1) * 8;
        const uint32_t bq    = ks * 2 + ((lane >> 3) & 1);
#pragma unroll
        for (int pr = 0; pr < 2; pr++) {
            uint32_t bh0, bh1, bh2, bh3, bl0, bl1, bl2, bl3;
            const uint32_t adr = sbB + swz(brow0 + pr * 16, bq);
            ldmx4(bh0, bh1, bh2, bh3, adr);
            ldmx4(bl0, bl1, bl2, bl3, adr + OFF_BLO);
#pragma unroll
            for (int mt = 0; mt < 4; mt++) {
                float* c0 = acc[mt][2 * pr];
                mma16816(c0[0], c0[1], c0[2], c0[3],
                         ah[mt][0], ah[mt][1], ah[mt][2], ah[mt][3], bh0, bh1);
                mma16816(c0[0], c0[1], c0[2], c0[3],
                         ah[mt][0], ah[mt][1], ah[mt][2], ah[mt][3], bl0, bl1);
                mma16816(c0[0], c0[1], c0[2], c0[3],
                         al[mt][0], al[mt][1], al[mt][2], al[mt][3], bh0, bh1);
                float* c1 = acc[mt][2 * pr + 1];
                mma16816(c1[0], c1[1], c1[2], c1[3],
                         ah[mt][0], ah[mt][1], ah[mt][2], ah[mt][3], bh2, bh3);
                mma16816(c1[0], c1[1], c1[2], c1[3],
                         ah[mt][0], ah[mt][1], ah[mt][2], ah[mt][3], bl2, bl3);
                mma16816(c1[0], c1[1], c1[2], c1[3],
                         al[mt][0], al[mt][1], al[mt][2], al[mt][3], bh2, bh3);
            }
        }
    }
}

// ---------------------------------------------------------------------------
// GEMM1: h1raw = x @ W1^T + b1 (fp32) + per-colblock LN partials.
// A: coalesced LDG fp32 -> reg split -> STS (3-buf ring). 1 barrier/stage.
// ---------------------------------------------------------------------------
__global__ void __launch_bounds__(256, 2)
gemm1_fused_kernel(const float* __restrict__ X,
                   const __nv_bfloat16* __restrict__ Bhi, const __nv_bfloat16* __restrict__ Blo,
                   const float* __restrict__ bias, float* __restrict__ C,
                   float2* __restrict__ gpart, int Mtot)
{
    constexpr int K = 512;
    constexpr int NSTAGES = K / 32;
    extern __shared__ char smem[];
    __shared__ float2 sred[4][128];
    const uint32_t sb = smem_u32(smem);

    const int tid   = threadIdx.x;
    const int lane  = tid & 31;
    const int wid   = tid >> 5;
    const int warpM = wid >> 2;
    const int warpN = wid & 3;
    const size_t rowBase = (size_t)blockIdx.y * 128;
    const int    colBase = blockIdx.x * 128;

    const int c0r = tid >> 2,  cq = tid & 3;
    const int c1r = 64 + c0r;
    const uint32_t d0 = swz(c0r, cq);
    const uint32_t d1 = swz(c1r, cq);

    // A fp32 sources: row c0r/c1r, 8 cols at cq*8 (coalesced: 4 thr = 128B)
    const float* a0p = X + (rowBase + c0r) * K + cq * 8;
    const float* a1p = X + (rowBase + c1r) * K + cq * 8;

    float acc[4][4][4];
#pragma unroll
    for (int i = 0; i < 4; i++)
#pragma unroll
        for (int j = 0; j < 4; j++)
#pragma unroll
            for (int q = 0; q < 4; q++) acc[i][j][q] = 0.f;

    float4 fA[4];
    auto prefetchA = [&](int t) {
        fA[0] = *reinterpret_cast<const float4*>(a0p + t * 32);
        fA[1] = *reinterpret_cast<const float4*>(a0p + t * 32 + 4);
        fA[2] = *reinterpret_cast<const float4*>(a1p + t * 32);
        fA[3] = *reinterpret_cast<const float4*>(a1p + t * 32 + 4);
    };
    auto load_B = [&](int t) {
        const int k0 = t * 32;
        const uint32_t s = sb + (t % 3) * B_STG;
        const size_t g0 = (size_t)(colBase + c0r) * K + k0 + cq * 8;
        const size_t g1 = (size_t)(colBase + c1r) * K + k0 + cq * 8;
        cp_async16(s + d0,           Bhi + g0);
        cp_async16(s + d1,           Bhi + g1);
        cp_async16(s + OFF_BLO + d0, Blo + g0);
        cp_async16(s + OFF_BLO + d1, Blo + g1);
        CP_COMMIT();
    };

    prefetchA(0);
    load_B(0);
    load_B(1);

#pragma unroll 1
    for (int t = 0; t < NSTAGES; t++) {
        // convert A(t): split, regs -> smem buffer t%3 (one uint4 hi + lo per row-slot)
        {
            const uint32_t abase = OFF_A + (t % 3) * A_STG;
            uint32_t hw[4], lw[4];
            split2(fA[0].x, fA[0].y, hw[0], lw[0]);
            split2(fA[0].z, fA[0].w, hw[1], lw[1]);
            split2(fA[1].x, fA[1].y, hw[2], lw[2]);
            split2(fA[1].z, fA[1].w, hw[3], lw[3]);
            *reinterpret_cast<uint4*>(smem + abase + d0) =
                make_uint4(hw[0], hw[1], hw[2], hw[3]);
            *reinterpret_cast<uint4*>(smem + abase + OFF_ALO + d0) =
                make_uint4(lw[0], lw[1], lw[2], lw[3]);
            split2(fA[2].x, fA[2].y, hw[0], lw[0]);
            split2(fA[2].z, fA[2].w, hw[1], lw[1]);
            split2(fA[3].x, fA[3].y, hw[2], lw[2]);
            split2(fA[3].z, fA[3].w, hw[3], lw[3]);
            *reinterpret_cast<uint4*>(smem + abase + d1) =
                make_uint4(hw[0], hw[1], hw[2], hw[3]);
            *reinterpret_cast<uint4*>(smem + abase + OFF_ALO + d1) =
                make_uint4(lw[0], lw[1], lw[2], lw[3]);
        }
        if (t + 1 < NSTAGES) prefetchA(t + 1);
        if (t + 1 < NSTAGES) { CP_WAIT(1); } else { CP_WAIT(0); }
        __syncthreads();
        if (t + 2 < NSTAGES) load_B(t + 2);

        mma_stage(sb + OFF_A + (t % 3) * A_STG, sb + (t % 3) * B_STG,
                  lane, warpM, warpN, acc);
        // no trailing barrier: A buf t%3 reused at t+3, safe past barrier(t+2)
    }

    // ---- epilogue: + bias, fp32 out, per-row partials ----
#pragma unroll
    for (int mt = 0; mt < 4; mt++) {
        const int rloc = warpM * 64 + mt * 16 + (lane >> 2);
        const size_t r0 = rowBase + rloc;
        float s0 = 0.f, q0 = 0.f, s1 = 0.f, q1 = 0.f;
#pragma unroll
        for (int nt = 0; nt < 4; nt++) {
            const int col = colBase + warpN * 32 + nt * 8 + (lane & 3) * 2;
            const float b0 = bias[col], b1 = bias[col + 1];
            float* c = acc[mt][nt];
            const float v00 = c[0] + b0, v01 = c[1] + b1;
            const float v10 = c[2] + b0, v11 = c[3] + b1;
            *reinterpret_cast<float2*>(C + r0 * 512 + col)       = make_float2(v00, v01);
            *reinterpret_cast<float2*>(C + (r0 + 8) * 512 + col) = make_float2(v10, v11);
            s0 += v00 + v01; q0 += v00 * v00 + v01 * v01;
            s1 += v10 + v11; q1 += v10 * v10 + v11 * v11;
        }
#pragma unroll
        for (int o = 1; o <= 2; o <<= 1) {
            s0 += __shfl_xor_sync(0xffffffffu, s0, o);
            q0 += __shfl_xor_sync(0xffffffffu, q0, o);
            s1 += __shfl_xor_sync(0xffffffffu, s1, o);
            q1 += __shfl_xor_sync(0xffffffffu, q1, o);
        }
        if ((lane & 3) == 0) {
            sred[warpN][rloc]     = make_float2(s0, q0);
            sred[warpN][rloc + 8] = make_float2(s1, q1);
        }
    }
    __syncthreads();
    if (tid < 128) {
        float s = 0.f, q = 0.f;
#pragma unroll
        for (int w = 0; w < 4; w++) { s += sred[w][tid].x; q += sred[w][tid].y; }
        gpart[(size_t)blockIdx.x * Mtot + rowBase + tid] = make_float2(s, q);
    }
}

// ---------------------------------------------------------------------------
// GEMM2 fused: a1 = celu(LN1(h1raw)) in regs -> HMMA bf16x3 -> LN2+CELU -> h2
// ---------------------------------------------------------------------------
__global__ void __launch_bounds__(256, 2)
gemm2_fused_kernel(const float* __restrict__ h1raw, const float2* __restrict__ gpart,
                   const float* __restrict__ g1, const float* __restrict__ be1,
                   const __nv_bfloat16* __restrict__ Bhi, const __nv_bfloat16* __restrict__ Blo,
                   const float* __restrict__ b2, const float* __restrict__ g2,
                   const float* __restrict__ be2,
                   float* __restrict__ h2, int Mtot)
{
    constexpr int K = 512;
    constexpr int NSTAGES = K / 32;
    extern __shared__ char smem[];
    __shared__ float  smu[128], srstd[128];
    __shared__ float  sg1[512], sbe1[512];
    __shared__ float  sg2[128], sbe2[128], sb2[128];
    __shared__ float2 sred[4][128];
    const uint32_t sb = smem_u32(smem);

    const int tid   = threadIdx.x;
    const int lane  = tid & 31;
    const int wid   = tid >> 5;
    const int warpM = wid >> 2;
    const int warpN = wid & 3;
    const size_t rowBase = (size_t)blockIdx.x * 128;

    if (tid < 128) {
        float s = 0.f, q = 0.f;
#pragma unroll
        for (int b = 0; b < 4; b++) {
            float2 p = gpart[(size_t)b * Mtot + rowBase + tid];
            s += p.x; q += p.y;
        }
        const float mu = s * (1.f / 512.f);
        smu[tid]   = mu;
        srstd[tid] = rsqrtf(q * (1.f / 512.f) - mu * mu + 1e-5f);
        sg2[tid] = g2[tid]; sbe2[tid] = be2[tid]; sb2[tid] = b2[tid];
    }
#pragma unroll
    for (int i = tid; i < 512; i += 256) { sg1[i] = g1[i]; sbe1[i] = be1[i]; }
    __syncthreads();

    const int c0r = tid >> 2,  cq = tid & 3;
    const int c1r = 64 + c0r;
    const uint32_t d0 = swz(c0r, cq);
    const uint32_t d1 = swz(c1r, cq);

    const float* a0p = h1raw + (rowBase + c0r) * K + cq * 8;
    const float* a1p = h1raw + (rowBase + c1r) * K + cq * 8;
    const float mu0 = smu[c0r], rs0 = srstd[c0r];
    const float mu1 = smu[c1r], rs1 = srstd[c1r];

    float acc[4][4][4];
#pragma unroll
    for (int i = 0; i < 4; i++)
#pragma unroll
        for (int j = 0; j < 4; j++)
#pragma unroll
            for (int q = 0; q < 4; q++) acc[i][j][q] = 0.f;

    float4 fA[4];
    auto prefetchA = [&](int t) {
        fA[0] = *reinterpret_cast<const float4*>(a0p + t * 32);
        fA[1] = *reinterpret_cast<const float4*>(a0p + t * 32 + 4);
        fA[2] = *reinterpret_cast<const float4*>(a1p + t * 32);
        fA[3] = *reinterpret_cast<const float4*>(a1p + t * 32 + 4);
    };
    auto load_B = [&](int t) {
        const int k0 = t * 32;
        const uint32_t s = sb + (t % 3) * B_STG;
        const size_t g0 = (size_t)c0r * K + k0 + cq * 8;
        const size_t g1 = (size_t)c1r * K + k0 + cq * 8;
        cp_async16(s + d0,           Bhi + g0);
        cp_async16(s + d1,           Bhi + g1);
        cp_async16(s + OFF_BLO + d0, Blo + g0);
        cp_async16(s + OFF_BLO + d1, Blo + g1);
        CP_COMMIT();
    };

    prefetchA(0);
    load_B(0);
    load_B(1);

#pragma unroll 1
    for (int t = 0; t < NSTAGES; t++) {
        // convert A(t): LN1 + CELU + split -> buffer t%3
        {
            const uint32_t abase = OFF_A + (t % 3) * A_STG;
            const int kcol = t * 32 + cq * 8;
            uint32_t hw[4], lw[4];
            // row c0r
#pragma unroll
            for (int j = 0; j < 2; j++) {
                const float* v = (j == 0) ? &fA[0].x : &fA[1].x;
#pragma unroll
                for (int e = 0; e < 2; e++) {
                    const int col = kcol + j * 4 + e * 2;
                    float y0 = celu1((v[2*e]   - mu0) * rs0 * sg1[col]     + sbe1[col]);
                    float y1 = celu1((v[2*e+1] - mu0) * rs0 * sg1[col + 1] + sbe1[col + 1]);
                    split2(y0, y1, hw[2 * j + e], lw[2 * j + e]);
                }
            }
            *reinterpret_cast<uint4*>(smem + abase + d0) =
                make_uint4(hw[0], hw[1], hw[2], hw[3]);
            *reinterpret_cast<uint4*>(smem + abase + OFF_ALO + d0) =
                make_uint4(lw[0], lw[1], lw[2], lw[3]);
            // row c1r
#pragma unroll
            for (int j = 0; j < 2; j++) {
                const float* v = (j == 0) ? &fA[2].x : &fA[3].x;
#pragma unroll
                for (int e = 0; e < 2; e++) {
                    const int col = kcol + j * 4 + e * 2;
                    float y0 = celu1((v[2*e]   - mu1) * rs1 * sg1[col]     + sbe1[col]);
                    float y1 = celu1((v[2*e+1] - mu1) * rs1 * sg1[col + 1] + sbe1[col + 1]);
                    split2(y0, y1, hw[2 * j + e], lw[2 * j + e]);
                }
            }
            *reinterpret_cast<uint4*>(smem + abase + d1) =
                make_uint4(hw[0], hw[1], hw[2], hw[3]);
            *reinterpret_cast<uint4*>(smem + abase + OFF_ALO + d1) =
                make_uint4(lw[0], lw[1], lw[2], lw[3]);
        }
        if (t + 1 < NSTAGES) prefetchA(t + 1);
        if (t + 1 < NSTAGES) { CP_WAIT(1); } else { CP_WAIT(0); }
        __syncthreads();
        if (t + 2 < NSTAGES) load_B(t + 2);

        mma_stage(sb + OFF_A + (t % 3) * A_STG, sb + (t % 3) * B_STG,
                  lane, warpM, warpN, acc);
    }

    // ---- epilogue: bias2, LN2 over full rows, CELU -> h2 ----
#pragma unroll
    for (int mt = 0; mt < 4; mt++) {
        const int rloc = warpM * 64 + mt * 16 + (lane >> 2);
        float s0 = 0.f, q0 = 0.f, s1 = 0.f, q1 = 0.f;
#pragma unroll
        for (int nt = 0; nt < 4; nt++) {
            const int col = warpN * 32 + nt * 8 + (lane & 3) * 2;
            const float b0 = sb2[col], b1 = sb2[col + 1];
            float* c = acc[mt][nt];
            const float v00 = c[0] + b0, v01 = c[1] + b1;
            const float v10 = c[2] + b0, v11 = c[3] + b1;
            s0 += v00 + v01; q0 += v00 * v00 + v01 * v01;
            s1 += v10 + v11; q1 += v10 * v10 + v11 * v11;
        }
#pragma unroll
        for (int o = 1; o <= 2; o <<= 1) {
            s0 += __shfl_xor_sync(0xffffffffu, s0, o);
            q0 += __shfl_xor_sync(0xffffffffu, q0, o);
            s1 += __shfl_xor_sync(0xffffffffu, s1, o);
            q1 += __shfl_xor_sync(0xffffffffu, q1, o);
        }
        if ((lane & 3) == 0) {
            sred[warpN][rloc]     = make_float2(s0, q0);
            sred[warpN][rloc + 8] = make_float2(s1, q1);
        }
    }
    __syncthreads();
    if (tid < 128) {
        float s = 0.f, q = 0.f;
#pragma unroll
        for (int w = 0; w < 4; w++) { s += sred[w][tid].x; q += sred[w][tid].y; }
        const float mu = s * (1.f / 128.f);
        smu[tid]   = mu;
        srstd[tid] = rsqrtf(q * (1.f / 128.f) - mu * mu + 1e-5f);
    }
    __syncthreads();
#pragma unroll
    for (int mt = 0; mt < 4; mt++) {
        const int rloc = warpM * 64 + mt * 16 + (lane >> 2);
        const float m0 = smu[rloc],     r0s = srstd[rloc];
        const float m1 = smu[rloc + 8], r1s = srstd[rloc + 8];
        const size_t r0 = rowBase + rloc;
#pragma unroll
        for (int nt = 0; nt < 4; nt++) {
            const int col = warpN * 32 + nt * 8 + (lane & 3) * 2;
            const float b0 = sb2[col], b1 = sb2[col + 1];
            float* c = acc[mt][nt];
            float y00 = (c[0] + b0 - m0) * r0s * sg2[col]     + sbe2[col];
            float y01 = (c[1] + b1 - m0) * r0s * sg2[col + 1] + sbe2[col + 1];
            float y10 = (c[2] + b0 - m1) * r1s * sg2[col]     + sbe2[col];
            float y11 = (c[3] + b1 - m1) * r1s * sg2[col + 1] + sbe2[col + 1];
            *reinterpret_cast<float2*>(h2 + r0 * 128 + col) =
                make_float2(celu1(y00), celu1(y01));
            *reinterpret_cast<float2*>(h2 + (r0 + 8) * 128 + col) =
                make_float2(celu1(y10), celu1(y11));
        }
    }
}

// ---------------------------------------------------------------------------
// Tail: layer3 (128->32)+LN+CELU, layer4 (32->8)+LN+CELU, spectral-norm head.
// ---------------------------------------------------------------------------
__global__ void __launch_bounds__(256)
tail_kernel(const float* __restrict__ h2,
            const float* __restrict__ W3, const float* __restrict__ b3,
            const float* __restrict__ g3, const float* __restrict__ be3,
            const float* __restrict__ W4, const float* __restrict__ b4,
            const float* __restrict__ g4, const float* __restrict__ be4,
            const float* __restrict__ Wh, const float* __restrict__ bh,
            const float* __restrict__ u, float* __restrict__ out)
{
    __shared__ float sW3[32 * 128];
    __shared__ float sW4[8 * 32];
    const int tid = threadIdx.x;
    for (int i = tid; i < 32 * 128; i += 256) sW3[i] = W3[i];
    if (tid < 8 * 32) sW4[tid] = W4[tid];
    __syncthreads();

    const int lane = tid & 31;
    const size_t row = (size_t)blockIdx.x * 8 + (tid >> 5);
    const float* rp = h2 + row * 128;
    const float r0 = rp[lane], r1 = rp[lane + 32], r2 = rp[lane + 64], r3 = rp[lane + 96];

    float h3 = 0.f;
#pragma unroll
    for (int j = 0; j < 32; j++) {
        const float* w = sW3 + j * 128;
        float p = r0 * w[lane] + r1 * w[lane + 32] + r2 * w[lane + 64] + r3 * w[lane + 96];
        p = warp_sum(p);
        if (lane == j) h3 = p + b3[j];
    }
    float mu  = warp_sum(h3) * (1.f / 32.f);
    float d   = h3 - mu;
    float var = warp_sum(d * d) * (1.f / 32.f);
    float y3  = d * rsqrtf(var + 1e-5f) * g3[lane] + be3[lane];
    const float c3 = (y3 > 0.f) ? y3 : expm1f(y3);

    float h4 = 0.f;
#pragma unroll
    for (int j = 0; j < 8; j++) {
        float p = warp_sum(c3 * sW4[j * 32 + lane]);
        if (lane == j) h4 = p + b4[j];
    }
    const bool act = (lane < 8);
    float hv = act ? h4 : 0.f;
    mu  = warp_sum(hv) * 0.125f;
    d   = act ? (h4 - mu) : 0.f;
    var = warp_sum(d * d) * 0.125f;
    float c4 = 0.f;
    if (act) {
        float y4 = d * rsqrtf(var + 1e-5f) * g4[lane] + be4[lane];
        c4 = (y4 > 0.f) ? y4 : expm1f(y4);
    }

    const float wh  = act ? Wh[lane] : 0.f;
    const float nrm = sqrtf(warp_sum(wh * wh));
    const float u0  = u[0];
    const float vden = fabsf(u0) * nrm + 1e-12f;
    const float t    = u0 * nrm * nrm / vden;
    const float u2n  = t / (fabsf(t) + 1e-12f);
    const float sigma = u2n * t;

    float p = warp_sum(c4 * wh / sigma);
    if (lane == 0) out[row] = p + bh[0];
}

// ---------------------------------------------------------------------------
extern "C" void kernel_launch(void* const* d_in, const int* in_sizes, int n_in,
                              void* d_out, int out_size)
{
    const float* x   = (const float*)d_in[0];
    const float* W1  = (const float*)d_in[1];
    const float* b1  = (const float*)d_in[2];
    const float* g1  = (const float*)d_in[3];
    const float* be1 = (const float*)d_in[4];
    const float* W2  = (const float*)d_in[5];
    const float* b2  = (const float*)d_in[6];
    const float* g2  = (const float*)d_in[7];
    const float* be2 = (const float*)d_in[8];
    const float* W3  = (const float*)d_in[9];
    const float* b3  = (const float*)d_in[10];
    const float* g3  = (const float*)d_in[11];
    const float* be3 = (const float*)d_in[12];
    const float* W4  = (const float*)d_in[13];
    const float* b4  = (const float*)d_in[14];
    const float* g4  = (const float*)d_in[15];
    const float* be4 = (const float*)d_in[16];
    const float* Wh  = (const float*)d_in[17];
    const float* bh  = (const float*)d_in[18];
    const float* u   = (const float*)d_in[19];
    float* out = (float*)d_out;

    const int M = in_sizes[0] / 512;   // 131072

    __nv_bfloat16 *w1hi, *w1lo, *w2hi, *w2lo;
    float *h1raw, *h2;
    float2* part;
    cudaGetSymbolAddress((void**)&h1raw, g_h1raw);
    cudaGetSymbolAddress((void**)&h2,    g_h2);
    cudaGetSymbolAddress((void**)&part,  g_part);
    cudaGetSymbolAddress((void**)&w1hi,  g_w1hi);
    cudaGetSymbolAddress((void**)&w1lo,  g_w1lo);
    cudaGetSymbolAddress((void**)&w2hi,  g_w2hi);
    cudaGetSymbolAddress((void**)&w2lo,  g_w2lo);

    cudaFuncSetAttribute(gemm1_fused_kernel,
                         cudaFuncAttributeMaxDynamicSharedMemorySize, SMEM_DYN);
    cudaFuncSetAttribute(gemm2_fused_kernel,
                         cudaFuncAttributeMaxDynamicSharedMemorySize, SMEM_DYN);

    // Split weights to bf16 hi/lo (small)
    split_kernel<<<(512 * 512 / 4 + 255) / 256, 256>>>(W1, w1hi, w1lo, 512 * 512 / 4);
    split_kernel<<<(128 * 512 / 4 + 255) / 256, 256>>>(W2, w2hi, w2lo, 128 * 512 / 4);

    // Layer 1: fused split(x)+GEMM -> h1raw fp32 + LN partials
    gemm1_fused_kernel<<<dim3(4, M / 128), 256, SMEM_DYN>>>(
        x, w1hi, w1lo, b1, h1raw, part, M);

    // Layer 2: fused LN1+CELU+split -> GEMM -> LN2+CELU -> h2
    gemm2_fused_kernel<<<M / 128, 256, SMEM_DYN>>>(
        h1raw, part, g1, be1, w2hi, w2lo, b2, g2, be2, h2, M);

    // Layers 3+4 + spectral-norm head
    tail_kernel<<<M / 8, 256>>>(h2, W3, b3, g3, be3, W4, b4, g4, be4, Wh, bh, u, out);
}